// round 5
// baseline (speedup 1.0000x reference)
#include <cuda_runtime.h>
#include <cuda_bf16.h>
#include <cstdint>

#define N_NODES 50000
#define N_EDGES 600000
#define LATENT 128
#define IN_FEAT 7
#define STEPS 3

// -------- scratch (static device globals; no allocation) --------
__device__ float g_h [N_NODES * LATENT];
__device__ float g_x2[N_NODES * LATENT];
__device__ float g_inv_s[N_NODES];
__device__ int   g_cnt_s[N_NODES];
__device__ int   g_cnt_r[N_NODES];
__device__ int   g_off  [N_NODES + 1];
__device__ int   g_cursor[N_NODES];
__device__ int   g_esrc [N_EDGES];

// ---------------- prologue ----------------
__global__ void k_zero() {
    int i = blockIdx.x * blockDim.x + threadIdx.x;
    if (i < N_NODES) { g_cnt_s[i] = 0; g_cnt_r[i] = 0; }
}

__global__ void k_count(const int* __restrict__ snd, const int* __restrict__ rcv) {
    int e = blockIdx.x * blockDim.x + threadIdx.x;
    if (e < N_EDGES) {
        atomicAdd(&g_cnt_s[snd[e]], 1);
        atomicAdd(&g_cnt_r[rcv[e]], 1);
    }
}

// single-block scan over receiver counts; also emits inv_sqrt of sender degree
__global__ __launch_bounds__(1024) void k_scan_all() {
    __shared__ int warp_sums[32];
    const int t = threadIdx.x;
    const int lane = t & 31;
    const int wid = t >> 5;
    int base = 0;

    const int NT = (N_NODES + 1023) / 1024;  // 49
    for (int j = 0; j < NT; j++) {
        int i = j * 1024 + t;
        int v = (i < N_NODES) ? g_cnt_r[i] : 0;
        int x = v;
        #pragma unroll
        for (int d = 1; d < 32; d <<= 1) {
            int y = __shfl_up_sync(0xFFFFFFFFu, x, d);
            if (lane >= d) x += y;
        }
        if (lane == 31) warp_sums[wid] = x;
        __syncthreads();
        if (t < 32) {
            int y = warp_sums[t];
            #pragma unroll
            for (int d = 1; d < 32; d <<= 1) {
                int z = __shfl_up_sync(0xFFFFFFFFu, y, d);
                if (t >= d) y += z;
            }
            warp_sums[t] = y;
        }
        __syncthreads();
        int incl = x + (wid ? warp_sums[wid - 1] : 0);
        int total = warp_sums[31];
        int excl = base + incl - v;
        if (i < N_NODES) {
            g_off[i] = excl;
            g_cursor[i] = excl;
            g_inv_s[i] = rsqrtf(fmaxf((float)g_cnt_s[i], 1.0f));
        }
        base += total;
        __syncthreads();
    }
    if (t == 0) g_off[N_NODES] = N_EDGES;
}

__global__ void k_fill(const int* __restrict__ snd, const int* __restrict__ rcv) {
    int e = blockIdx.x * blockDim.x + threadIdx.x;
    if (e < N_EDGES) {
        int r = rcv[e];
        int pos = atomicAdd(&g_cursor[r], 1);
        g_esrc[pos] = snd[e];
    }
}

// ---------------- embed ----------------
__global__ void k_embed(const float* __restrict__ nodes,
                        const float* __restrict__ Wemb,
                        const float* __restrict__ bemb) {
    int idx = blockIdx.x * blockDim.x + threadIdx.x;
    if (idx >= N_NODES * LATENT) return;
    int n = idx >> 7;
    int c = idx & 127;
    float acc = bemb[c];
    #pragma unroll
    for (int k = 0; k < IN_FEAT; k++)
        acc = fmaf(nodes[n * IN_FEAT + k], Wemb[k * LATENT + c], acc);
    g_h[idx] = acc;
}

// ---------------- fused dual GEMM (LDS-lean inner loop) ----------------
// x2 = relu( relu(h @ W0 + b0) @ W1 + b1 )   for a 64-row stripe.
// A chunks staged row-major; A-operand read as warp-broadcast float4 along k.
__global__ __launch_bounds__(256) void k_gemm2(const float* __restrict__ W0,
                                               const float* __restrict__ b0,
                                               const float* __restrict__ W1,
                                               const float* __restrict__ b1) {
    const float* __restrict__ A = g_h;
    float* __restrict__ C = g_x2;

    __shared__ float As[64][16];      // stage-1 A chunk, row-major
    __shared__ float Ws[16][128];     // weight chunk [k][col]
    __shared__ float X1[64 * 128];    // intermediate tile [row][col]

    const int tid = threadIdx.x;
    const int tx = tid & 31;          // col group (cols tx*4 .. +3)
    const int ty = tid >> 5;          // row group (rows ty*8 .. +7)
    const int rowBase = blockIdx.x * 64;

    // stagers
    const int ar = tid >> 2;          // 0..63
    const int kq = (tid & 3) * 4;     // 0,4,8,12
    const int wr = tid >> 5;          // 0..7
    const int wc = (tid & 31) * 4;    // 0..124

    float acc[8][4];
    #pragma unroll
    for (int i = 0; i < 8; i++)
        #pragma unroll
        for (int j = 0; j < 4; j++) acc[i][j] = 0.f;

    // ---------- stage 1: X1 = relu(A @ W0 + b0) ----------
    const bool arOK = (rowBase + ar) < N_NODES;
    for (int k0 = 0; k0 < 128; k0 += 16) {
        {
            float4 v = arOK ? *(const float4*)&A[(size_t)(rowBase + ar) * 128 + k0 + kq]
                            : make_float4(0.f, 0.f, 0.f, 0.f);
            *(float4*)&As[ar][kq] = v;
            *(float4*)&Ws[wr][wc]     = *(const float4*)&W0[(k0 + wr) * 128 + wc];
            *(float4*)&Ws[wr + 8][wc] = *(const float4*)&W0[(k0 + wr + 8) * 128 + wc];
        }
        __syncthreads();
        #pragma unroll
        for (int k4 = 0; k4 < 16; k4 += 4) {
            float4 av[8];
            #pragma unroll
            for (int i = 0; i < 8; i++)
                av[i] = *(const float4*)&As[ty * 8 + i][k4];   // warp broadcast
            #pragma unroll
            for (int kk = 0; kk < 4; kk++) {
                float4 wv = *(const float4*)&Ws[k4 + kk][tx * 4];
                #pragma unroll
                for (int i = 0; i < 8; i++) {
                    float a = (kk == 0) ? av[i].x : (kk == 1) ? av[i].y
                            : (kk == 2) ? av[i].z : av[i].w;
                    acc[i][0] = fmaf(a, wv.x, acc[i][0]);
                    acc[i][1] = fmaf(a, wv.y, acc[i][1]);
                    acc[i][2] = fmaf(a, wv.z, acc[i][2]);
                    acc[i][3] = fmaf(a, wv.w, acc[i][3]);
                }
            }
        }
        __syncthreads();
    }
    {
        float4 bv = *(const float4*)&b0[tx * 4];
        #pragma unroll
        for (int i = 0; i < 8; i++) {
            float4 o;
            o.x = fmaxf(acc[i][0] + bv.x, 0.f);
            o.y = fmaxf(acc[i][1] + bv.y, 0.f);
            o.z = fmaxf(acc[i][2] + bv.z, 0.f);
            o.w = fmaxf(acc[i][3] + bv.w, 0.f);
            *(float4*)&X1[(ty * 8 + i) * 128 + tx * 4] = o;
        }
    }
    __syncthreads();

    // ---------- stage 2: x2 = relu(X1 @ W1 + b1) ----------
    #pragma unroll
    for (int i = 0; i < 8; i++)
        #pragma unroll
        for (int j = 0; j < 4; j++) acc[i][j] = 0.f;

    for (int k0 = 0; k0 < 128; k0 += 16) {
        *(float4*)&Ws[wr][wc]     = *(const float4*)&W1[(k0 + wr) * 128 + wc];
        *(float4*)&Ws[wr + 8][wc] = *(const float4*)&W1[(k0 + wr + 8) * 128 + wc];
        __syncthreads();
        #pragma unroll
        for (int k4 = 0; k4 < 16; k4 += 4) {
            float4 av[8];
            #pragma unroll
            for (int i = 0; i < 8; i++)
                av[i] = *(const float4*)&X1[(ty * 8 + i) * 128 + k0 + k4];  // broadcast
            #pragma unroll
            for (int kk = 0; kk < 4; kk++) {
                float4 wv = *(const float4*)&Ws[k4 + kk][tx * 4];
                #pragma unroll
                for (int i = 0; i < 8; i++) {
                    float a = (kk == 0) ? av[i].x : (kk == 1) ? av[i].y
                            : (kk == 2) ? av[i].z : av[i].w;
                    acc[i][0] = fmaf(a, wv.x, acc[i][0]);
                    acc[i][1] = fmaf(a, wv.y, acc[i][1]);
                    acc[i][2] = fmaf(a, wv.z, acc[i][2]);
                    acc[i][3] = fmaf(a, wv.w, acc[i][3]);
                }
            }
        }
        __syncthreads();
    }
    {
        float4 bv = *(const float4*)&b1[tx * 4];
        #pragma unroll
        for (int i = 0; i < 8; i++) {
            int row = rowBase + ty * 8 + i;
            if (row >= N_NODES) break;
            float4 o;
            o.x = fmaxf(acc[i][0] + bv.x, 0.f);
            o.y = fmaxf(acc[i][1] + bv.y, 0.f);
            o.z = fmaxf(acc[i][2] + bv.z, 0.f);
            o.w = fmaxf(acc[i][3] + bv.w, 0.f);
            *(float4*)&C[(size_t)row * 128 + tx * 4] = o;
        }
    }
}

// ---------------- fused aggregate (sender-scaled) + skip + LayerNorm ----------------
__global__ __launch_bounds__(256) void k_agg_ln(const float* __restrict__ ln_scale,
                                                const float* __restrict__ ln_bias) {
    int node = blockIdx.x * 8 + (threadIdx.x >> 5);
    if (node >= N_NODES) return;
    int lane = threadIdx.x & 31;

    int b0 = g_off[node], b1 = g_off[node + 1];
    float4 acc0 = make_float4(0.f, 0.f, 0.f, 0.f);
    float4 acc1 = make_float4(0.f, 0.f, 0.f, 0.f);
    int j = b0;
    for (; j + 1 < b1; j += 2) {
        int s0 = g_esrc[j];
        int s1 = g_esrc[j + 1];
        float is0 = g_inv_s[s0];
        float is1 = g_inv_s[s1];
        float4 v0 = *(const float4*)&g_x2[(size_t)s0 * 128 + lane * 4];
        float4 v1 = *(const float4*)&g_x2[(size_t)s1 * 128 + lane * 4];
        acc0.x = fmaf(v0.x, is0, acc0.x);
        acc0.y = fmaf(v0.y, is0, acc0.y);
        acc0.z = fmaf(v0.z, is0, acc0.z);
        acc0.w = fmaf(v0.w, is0, acc0.w);
        acc1.x = fmaf(v1.x, is1, acc1.x);
        acc1.y = fmaf(v1.y, is1, acc1.y);
        acc1.z = fmaf(v1.z, is1, acc1.z);
        acc1.w = fmaf(v1.w, is1, acc1.w);
    }
    if (j < b1) {
        int s0 = g_esrc[j];
        float is0 = g_inv_s[s0];
        float4 v0 = *(const float4*)&g_x2[(size_t)s0 * 128 + lane * 4];
        acc0.x = fmaf(v0.x, is0, acc0.x);
        acc0.y = fmaf(v0.y, is0, acc0.y);
        acc0.z = fmaf(v0.z, is0, acc0.z);
        acc0.w = fmaf(v0.w, is0, acc0.w);
    }
    float4 acc;
    acc.x = acc0.x + acc1.x;
    acc.y = acc0.y + acc1.y;
    acc.z = acc0.z + acc1.z;
    acc.w = acc0.w + acc1.w;

    float invr = rsqrtf(fmaxf((float)(b1 - b0), 1.0f));
    float4 hv = *(const float4*)&g_h[(size_t)node * 128 + lane * 4];
    float4 u;
    u.x = fmaf(acc.x, invr, hv.x);
    u.y = fmaf(acc.y, invr, hv.y);
    u.z = fmaf(acc.z, invr, hv.z);
    u.w = fmaf(acc.w, invr, hv.w);

    float sum = u.x + u.y + u.z + u.w;
    float sq  = u.x * u.x + u.y * u.y + u.z * u.z + u.w * u.w;
    #pragma unroll
    for (int d = 16; d > 0; d >>= 1) {
        sum += __shfl_xor_sync(0xFFFFFFFFu, sum, d);
        sq  += __shfl_xor_sync(0xFFFFFFFFu, sq, d);
    }
    float mean = sum * (1.0f / 128.0f);
    float var = sq * (1.0f / 128.0f) - mean * mean;
    float rstd = rsqrtf(var + 1e-6f);

    float4 sc = *(const float4*)&ln_scale[lane * 4];
    float4 bi = *(const float4*)&ln_bias[lane * 4];
    float4 o;
    o.x = (u.x - mean) * rstd * sc.x + bi.x;
    o.y = (u.y - mean) * rstd * sc.y + bi.y;
    o.z = (u.z - mean) * rstd * sc.z + bi.z;
    o.w = (u.w - mean) * rstd * sc.w + bi.w;
    *(float4*)&g_h[(size_t)node * 128 + lane * 4] = o;
}

// ---------------- decoder ----------------
__global__ __launch_bounds__(256) void k_decode(const float* __restrict__ Wdec,
                                                const float* __restrict__ bdec,
                                                float* __restrict__ out) {
    int node = blockIdx.x * 8 + (threadIdx.x >> 5);
    if (node >= N_NODES) return;
    int lane = threadIdx.x & 31;

    float4 hv = *(const float4*)&g_h[(size_t)node * 128 + lane * 4];
    #pragma unroll
    for (int j = 0; j < IN_FEAT; j++) {
        float p = hv.x * __ldg(&Wdec[(lane * 4 + 0) * IN_FEAT + j])
                + hv.y * __ldg(&Wdec[(lane * 4 + 1) * IN_FEAT + j])
                + hv.z * __ldg(&Wdec[(lane * 4 + 2) * IN_FEAT + j])
                + hv.w * __ldg(&Wdec[(lane * 4 + 3) * IN_FEAT + j]);
        #pragma unroll
        for (int d = 16; d > 0; d >>= 1)
            p += __shfl_xor_sync(0xFFFFFFFFu, p, d);
        if (lane == j) out[node * IN_FEAT + j] = p + bdec[j];
    }
}

extern "C" void kernel_launch(void* const* d_in, const int* in_sizes, int n_in,
                              void* d_out, int out_size) {
    const float* nodes    = (const float*)d_in[0];
    const int*   senders  = (const int*)  d_in[1];
    const int*   receivers= (const int*)  d_in[2];
    const float* W_embed  = (const float*)d_in[3];
    const float* b_embed  = (const float*)d_in[4];
    const float* mlp_W    = (const float*)d_in[5];
    const float* mlp_b    = (const float*)d_in[6];
    const float* ln_scale = (const float*)d_in[7];
    const float* ln_bias  = (const float*)d_in[8];
    const float* W_dec    = (const float*)d_in[9];
    const float* b_dec    = (const float*)d_in[10];
    float* out = (float*)d_out;

    const int GEMM_GRID = (N_NODES + 63) / 64;

    // launch index 3 = k_gemm2 (step 0) -> this is what ncu captures
    k_zero <<<(N_NODES + 255) / 256, 256>>>();                                   // 0
    k_count<<<(N_EDGES + 255) / 256, 256>>>(senders, receivers);                 // 1
    k_embed<<<(N_NODES * LATENT + 255) / 256, 256>>>(nodes, W_embed, b_embed);   // 2
    k_gemm2<<<GEMM_GRID, 256>>>(mlp_W, mlp_b,                                    // 3
                                mlp_W + (size_t)LATENT * LATENT, mlp_b + LATENT);
    k_scan_all<<<1, 1024>>>();                                                   // 4
    k_fill <<<(N_EDGES + 255) / 256, 256>>>(senders, receivers);                 // 5

    for (int step = 0; step < STEPS; step++) {
        if (step > 0) {
            const float* W0 = mlp_W + (size_t)(step * 2 + 0) * LATENT * LATENT;
            const float* W1 = mlp_W + (size_t)(step * 2 + 1) * LATENT * LATENT;
            const float* b0 = mlp_b + (size_t)(step * 2 + 0) * LATENT;
            const float* b1 = mlp_b + (size_t)(step * 2 + 1) * LATENT;
            k_gemm2<<<GEMM_GRID, 256>>>(W0, b0, W1, b1);
        }
        k_agg_ln<<<(N_NODES + 7) / 8, 256>>>(ln_scale + step * LATENT,
                                             ln_bias + step * LATENT);
    }

    k_decode<<<(N_NODES + 7) / 8, 256>>>(W_dec, b_dec, out);
}

// round 7
// speedup vs baseline: 1.0361x; 1.0361x over previous
#include <cuda_runtime.h>
#include <cuda_bf16.h>
#include <cstdint>

#define N_NODES 50000
#define N_PAD   50048            // 782 * 64
#define N_EDGES 600000
#define LATENT 128
#define IN_FEAT 7
#define STEPS 3

// -------- scratch (static device globals; zero-initialized, no allocation) ----
__device__ float g_h [N_PAD * LATENT];
__device__ float g_x2[N_PAD * LATENT];
__device__ float g_inv_s[N_NODES];
__device__ int   g_cnt_s[N_NODES];
__device__ int   g_cnt_r[N_NODES];
__device__ int   g_off  [N_NODES + 1];
__device__ int   g_cursor[N_NODES];
__device__ int   g_esrc [N_EDGES];

// ---------------- cp.async helpers (sm_80+; no 'a' features needed) ----------
__device__ __forceinline__ void cp16(uint32_t dst, const void* src) {
    asm volatile("cp.async.ca.shared.global [%0], [%1], 16;" :: "r"(dst), "l"(src));
}
__device__ __forceinline__ void cp_commit() {
    asm volatile("cp.async.commit_group;");
}
template <int N>
__device__ __forceinline__ void cp_wait() {
    asm volatile("cp.async.wait_group %0;" :: "n"(N));
}

// ---------------- prologue ----------------
__global__ void k_zero() {
    int i = blockIdx.x * blockDim.x + threadIdx.x;
    if (i < N_NODES) { g_cnt_s[i] = 0; g_cnt_r[i] = 0; }
}

__global__ void k_count(const int* __restrict__ snd, const int* __restrict__ rcv) {
    int e = blockIdx.x * blockDim.x + threadIdx.x;
    if (e < N_EDGES) {
        atomicAdd(&g_cnt_s[snd[e]], 1);
        atomicAdd(&g_cnt_r[rcv[e]], 1);
    }
}

__global__ __launch_bounds__(1024) void k_scan_all() {
    __shared__ int warp_sums[32];
    const int t = threadIdx.x;
    const int lane = t & 31;
    const int wid = t >> 5;
    int base = 0;

    const int NT = (N_NODES + 1023) / 1024;
    for (int j = 0; j < NT; j++) {
        int i = j * 1024 + t;
        int v = (i < N_NODES) ? g_cnt_r[i] : 0;
        int x = v;
        #pragma unroll
        for (int d = 1; d < 32; d <<= 1) {
            int y = __shfl_up_sync(0xFFFFFFFFu, x, d);
            if (lane >= d) x += y;
        }
        if (lane == 31) warp_sums[wid] = x;
        __syncthreads();
        if (t < 32) {
            int y = warp_sums[t];
            #pragma unroll
            for (int d = 1; d < 32; d <<= 1) {
                int z = __shfl_up_sync(0xFFFFFFFFu, y, d);
                if (t >= d) y += z;
            }
            warp_sums[t] = y;
        }
        __syncthreads();
        int incl = x + (wid ? warp_sums[wid - 1] : 0);
        int total = warp_sums[31];
        int excl = base + incl - v;
        if (i < N_NODES) {
            g_off[i] = excl;
            g_cursor[i] = excl;
            g_inv_s[i] = rsqrtf(fmaxf((float)g_cnt_s[i], 1.0f));
        }
        base += total;
        __syncthreads();
    }
    if (t == 0) g_off[N_NODES] = N_EDGES;
}

__global__ void k_fill(const int* __restrict__ snd, const int* __restrict__ rcv) {
    int e = blockIdx.x * blockDim.x + threadIdx.x;
    if (e < N_EDGES) {
        int r = rcv[e];
        int pos = atomicAdd(&g_cursor[r], 1);
        g_esrc[pos] = snd[e];
    }
}

// ---------------- embed ----------------
__global__ void k_embed(const float* __restrict__ nodes,
                        const float* __restrict__ Wemb,
                        const float* __restrict__ bemb) {
    int idx = blockIdx.x * blockDim.x + threadIdx.x;
    if (idx >= N_NODES * LATENT) return;
    int n = idx >> 7;
    int c = idx & 127;
    float acc = bemb[c];
    #pragma unroll
    for (int k = 0; k < IN_FEAT; k++)
        acc = fmaf(nodes[n * IN_FEAT + k], Wemb[k * LATENT + c], acc);
    g_h[idx] = acc;
}

// ---------------- fused dual GEMM, cp.async double-buffered ----------------
// x2 = relu( relu(h @ W0 + b0) @ W1 + b1 )  for a 64-row stripe (padded rows ok).
// Inner loop = R4's proven mix: 8 broadcast LDS + 1 LDS.128 + 32 FFMA per k.
__global__ __launch_bounds__(256) void k_gemm2(const float* __restrict__ W0,
                                               const float* __restrict__ b0,
                                               const float* __restrict__ W1,
                                               const float* __restrict__ b1) {
    __shared__ float As[2][64][16];    // A chunk, row-major, double-buffered
    __shared__ float Ws[2][16][128];   // weight chunk [k][col], double-buffered
    __shared__ float X1[64 * 128];     // intermediate tile

    const int tid = threadIdx.x;
    const int tx = tid & 31;           // col group (cols tx*4 .. +3)
    const int ty = tid >> 5;           // row group (rows ty*8 .. +7)
    const size_t rowBase = (size_t)blockIdx.x * 64;

    // loader mappings
    const int ar = tid >> 2;           // 0..63
    const int kq = (tid & 3) * 4;      // 0,4,8,12
    const int wr = tid >> 5;           // 0..7
    const int wc = (tid & 31) * 4;     // 0..124

    const float* Aptr = g_h + (rowBase + ar) * 128 + kq;

    uint32_t dA[2], dWa[2], dWb[2];
    dA[0]  = (uint32_t)__cvta_generic_to_shared(&As[0][ar][kq]);
    dA[1]  = (uint32_t)__cvta_generic_to_shared(&As[1][ar][kq]);
    dWa[0] = (uint32_t)__cvta_generic_to_shared(&Ws[0][wr][wc]);
    dWa[1] = (uint32_t)__cvta_generic_to_shared(&Ws[1][wr][wc]);
    dWb[0] = (uint32_t)__cvta_generic_to_shared(&Ws[0][wr + 8][wc]);
    dWb[1] = (uint32_t)__cvta_generic_to_shared(&Ws[1][wr + 8][wc]);

    float acc[8][4];
    #pragma unroll
    for (int i = 0; i < 8; i++)
        #pragma unroll
        for (int j = 0; j < 4; j++) acc[i][j] = 0.f;

    // ---------- stage 1: X1 = relu(A @ W0 + b0) ----------
    cp16(dA[0], Aptr);
    cp16(dWa[0], &W0[wr * 128 + wc]);
    cp16(dWb[0], &W0[(wr + 8) * 128 + wc]);
    cp_commit();

    #pragma unroll 1
    for (int t = 0; t < 8; t++) {
        const int buf = t & 1;
        if (t < 7) {
            const int nb = buf ^ 1;
            cp16(dA[nb], Aptr + (t + 1) * 16);
            cp16(dWa[nb], &W0[((t + 1) * 16 + wr) * 128 + wc]);
            cp16(dWb[nb], &W0[((t + 1) * 16 + wr + 8) * 128 + wc]);
            cp_commit();
            cp_wait<1>();
        } else {
            cp_wait<0>();
        }
        __syncthreads();
        #pragma unroll
        for (int k = 0; k < 16; k++) {
            float4 wv = *(const float4*)&Ws[buf][k][tx * 4];
            #pragma unroll
            for (int i = 0; i < 8; i++) {
                float a = As[buf][ty * 8 + i][k];     // warp broadcast
                acc[i][0] = fmaf(a, wv.x, acc[i][0]);
                acc[i][1] = fmaf(a, wv.y, acc[i][1]);
                acc[i][2] = fmaf(a, wv.z, acc[i][2]);
                acc[i][3] = fmaf(a, wv.w, acc[i][3]);
            }
        }
        __syncthreads();
    }

    // prefetch W1 chunk 0 while doing the X1 epilogue
    cp16(dWa[0], &W1[wr * 128 + wc]);
    cp16(dWb[0], &W1[(wr + 8) * 128 + wc]);
    cp_commit();

    {
        float4 bv = *(const float4*)&b0[tx * 4];
        #pragma unroll
        for (int i = 0; i < 8; i++) {
            float4 o;
            o.x = fmaxf(acc[i][0] + bv.x, 0.f);
            o.y = fmaxf(acc[i][1] + bv.y, 0.f);
            o.z = fmaxf(acc[i][2] + bv.z, 0.f);
            o.w = fmaxf(acc[i][3] + bv.w, 0.f);
            *(float4*)&X1[(ty * 8 + i) * 128 + tx * 4] = o;
            acc[i][0] = acc[i][1] = acc[i][2] = acc[i][3] = 0.f;
        }
    }

    // ---------- stage 2: x2 = relu(X1 @ W1 + b1) ----------
    #pragma unroll 1
    for (int t = 0; t < 8; t++) {
        const int buf = t & 1;
        if (t < 7) {
            const int nb = buf ^ 1;
            cp16(dWa[nb], &W1[((t + 1) * 16 + wr) * 128 + wc]);
            cp16(dWb[nb], &W1[((t + 1) * 16 + wr + 8) * 128 + wc]);
            cp_commit();
            cp_wait<1>();
        } else {
            cp_wait<0>();
        }
        __syncthreads();
        #pragma unroll
        for (int k = 0; k < 16; k++) {
            float4 wv = *(const float4*)&Ws[buf][k][tx * 4];
            #pragma unroll
            for (int i = 0; i < 8; i++) {
                float a = X1[(ty * 8 + i) * 128 + t * 16 + k];   // warp broadcast
                acc[i][0] = fmaf(a, wv.x, acc[i][0]);
                acc[i][1] = fmaf(a, wv.y, acc[i][1]);
                acc[i][2] = fmaf(a, wv.z, acc[i][2]);
                acc[i][3] = fmaf(a, wv.w, acc[i][3]);
            }
        }
        __syncthreads();
    }

    {
        float4 bv = *(const float4*)&b1[tx * 4];
        float* Crow = g_x2 + rowBase * 128;
        #pragma unroll
        for (int i = 0; i < 8; i++) {
            float4 o;
            o.x = fmaxf(acc[i][0] + bv.x, 0.f);
            o.y = fmaxf(acc[i][1] + bv.y, 0.f);
            o.z = fmaxf(acc[i][2] + bv.z, 0.f);
            o.w = fmaxf(acc[i][3] + bv.w, 0.f);
            *(float4*)&Crow[(ty * 8 + i) * 128 + tx * 4] = o;
        }
    }
}

// ---------------- fused aggregate (sender-scaled) + skip + LayerNorm ----------------
__global__ __launch_bounds__(256) void k_agg_ln(const float* __restrict__ ln_scale,
                                                const float* __restrict__ ln_bias) {
    int node = blockIdx.x * 8 + (threadIdx.x >> 5);
    if (node >= N_NODES) return;
    int lane = threadIdx.x & 31;

    int b0 = g_off[node], b1 = g_off[node + 1];
    float4 acc0 = make_float4(0.f, 0.f, 0.f, 0.f);
    float4 acc1 = make_float4(0.f, 0.f, 0.f, 0.f);
    int j = b0;
    for (; j + 1 < b1; j += 2) {
        int s0 = g_esrc[j];
        int s1 = g_esrc[j + 1];
        float is0 = g_inv_s[s0];
        float is1 = g_inv_s[s1];
        float4 v0 = *(const float4*)&g_x2[(size_t)s0 * 128 + lane * 4];
        float4 v1 = *(const float4*)&g_x2[(size_t)s1 * 128 + lane * 4];
        acc0.x = fmaf(v0.x, is0, acc0.x);
        acc0.y = fmaf(v0.y, is0, acc0.y);
        acc0.z = fmaf(v0.z, is0, acc0.z);
        acc0.w = fmaf(v0.w, is0, acc0.w);
        acc1.x = fmaf(v1.x, is1, acc1.x);
        acc1.y = fmaf(v1.y, is1, acc1.y);
        acc1.z = fmaf(v1.z, is1, acc1.z);
        acc1.w = fmaf(v1.w, is1, acc1.w);
    }
    if (j < b1) {
        int s0 = g_esrc[j];
        float is0 = g_inv_s[s0];
        float4 v0 = *(const float4*)&g_x2[(size_t)s0 * 128 + lane * 4];
        acc0.x = fmaf(v0.x, is0, acc0.x);
        acc0.y = fmaf(v0.y, is0, acc0.y);
        acc0.z = fmaf(v0.z, is0, acc0.z);
        acc0.w = fmaf(v0.w, is0, acc0.w);
    }
    float4 acc;
    acc.x = acc0.x + acc1.x;
    acc.y = acc0.y + acc1.y;
    acc.z = acc0.z + acc1.z;
    acc.w = acc0.w + acc1.w;

    float invr = rsqrtf(fmaxf((float)(b1 - b0), 1.0f));
    float4 hv = *(const float4*)&g_h[(size_t)node * 128 + lane * 4];
    float4 u;
    u.x = fmaf(acc.x, invr, hv.x);
    u.y = fmaf(acc.y, invr, hv.y);
    u.z = fmaf(acc.z, invr, hv.z);
    u.w = fmaf(acc.w, invr, hv.w);

    float sum = u.x + u.y + u.z + u.w;
    float sq  = u.x * u.x + u.y * u.y + u.z * u.z + u.w * u.w;
    #pragma unroll
    for (int d = 16; d > 0; d >>= 1) {
        sum += __shfl_xor_sync(0xFFFFFFFFu, sum, d);
        sq  += __shfl_xor_sync(0xFFFFFFFFu, sq, d);
    }
    float mean = sum * (1.0f / 128.0f);
    float var = sq * (1.0f / 128.0f) - mean * mean;
    float rstd = rsqrtf(var + 1e-6f);

    float4 sc = *(const float4*)&ln_scale[lane * 4];
    float4 bi = *(const float4*)&ln_bias[lane * 4];
    float4 o;
    o.x = (u.x - mean) * rstd * sc.x + bi.x;
    o.y = (u.y - mean) * rstd * sc.y + bi.y;
    o.z = (u.z - mean) * rstd * sc.z + bi.z;
    o.w = (u.w - mean) * rstd * sc.w + bi.w;
    *(float4*)&g_h[(size_t)node * 128 + lane * 4] = o;
}

// ---------------- decoder ----------------
__global__ __launch_bounds__(256) void k_decode(const float* __restrict__ Wdec,
                                                const float* __restrict__ bdec,
                                                float* __restrict__ out) {
    int node = blockIdx.x * 8 + (threadIdx.x >> 5);
    if (node >= N_NODES) return;
    int lane = threadIdx.x & 31;

    float4 hv = *(const float4*)&g_h[(size_t)node * 128 + lane * 4];
    #pragma unroll
    for (int j = 0; j < IN_FEAT; j++) {
        float p = hv.x * __ldg(&Wdec[(lane * 4 + 0) * IN_FEAT + j])
                + hv.y * __ldg(&Wdec[(lane * 4 + 1) * IN_FEAT + j])
                + hv.z * __ldg(&Wdec[(lane * 4 + 2) * IN_FEAT + j])
                + hv.w * __ldg(&Wdec[(lane * 4 + 3) * IN_FEAT + j]);
        #pragma unroll
        for (int d = 16; d > 0; d >>= 1)
            p += __shfl_xor_sync(0xFFFFFFFFu, p, d);
        if (lane == j) out[node * IN_FEAT + j] = p + bdec[j];
    }
}

extern "C" void kernel_launch(void* const* d_in, const int* in_sizes, int n_in,
                              void* d_out, int out_size) {
    const float* nodes    = (const float*)d_in[0];
    const int*   senders  = (const int*)  d_in[1];
    const int*   receivers= (const int*)  d_in[2];
    const float* W_embed  = (const float*)d_in[3];
    const float* b_embed  = (const float*)d_in[4];
    const float* mlp_W    = (const float*)d_in[5];
    const float* mlp_b    = (const float*)d_in[6];
    const float* ln_scale = (const float*)d_in[7];
    const float* ln_bias  = (const float*)d_in[8];
    const float* W_dec    = (const float*)d_in[9];
    const float* b_dec    = (const float*)d_in[10];
    float* out = (float*)d_out;

    const int GEMM_GRID = N_PAD / 64;    // 782

    // launch index 3 = k_gemm2 (step 0) -> what ncu captures
    k_zero <<<(N_NODES + 255) / 256, 256>>>();                                   // 0
    k_count<<<(N_EDGES + 255) / 256, 256>>>(senders, receivers);                 // 1
    k_embed<<<(N_NODES * LATENT + 255) / 256, 256>>>(nodes, W_embed, b_embed);   // 2
    k_gemm2<<<GEMM_GRID, 256>>>(mlp_W, mlp_b,                                    // 3
                                mlp_W + (size_t)LATENT * LATENT, mlp_b + LATENT);
    k_scan_all<<<1, 1024>>>();                                                   // 4
    k_fill <<<(N_EDGES + 255) / 256, 256>>>(senders, receivers);                 // 5

    for (int step = 0; step < STEPS; step++) {
        if (step > 0) {
            const float* W0 = mlp_W + (size_t)(step * 2 + 0) * LATENT * LATENT;
            const float* W1 = mlp_W + (size_t)(step * 2 + 1) * LATENT * LATENT;
            const float* b0 = mlp_b + (size_t)(step * 2 + 0) * LATENT;
            const float* b1 = mlp_b + (size_t)(step * 2 + 1) * LATENT;
            k_gemm2<<<GEMM_GRID, 256>>>(W0, b0, W1, b1);
        }
        k_agg_ln<<<(N_NODES + 7) / 8, 256>>>(ln_scale + step * LATENT,
                                             ln_bias + step * LATENT);
    }

    k_decode<<<(N_NODES + 7) / 8, 256>>>(W_dec, b_dec, out);
}